// round 2
// baseline (speedup 1.0000x reference)
#include <cuda_runtime.h>
#include <math.h>

// ---------------- problem constants ----------------
#define Bq    8
#define Nn    1024
#define Ff    128
#define Gg    64
#define Mm    4
#define Ee    3
#define EM    12          // E*M
#define HC    768         // M*E*G (hidden width)
#define ROWS  8192        // B*N
#define L0c   256
#define L1c   256
#define ALPHAc 0.5f
#define NEGV  (-9000000000000000.0f)
#define EPSc  1e-5f

typedef unsigned long long ull;

// ---------------- f32x2 helpers ----------------
__device__ __forceinline__ ull fma2(ull a, ull b, ull c) {
    ull d;
    asm("fma.rn.f32x2 %0, %1, %2, %3;" : "=l"(d) : "l"(a), "l"(b), "l"(c));
    return d;
}
__device__ __forceinline__ ull pack2(float x) {
    ull d; unsigned u = __float_as_uint(x);
    asm("mov.b64 %0, {%1, %1};" : "=l"(d) : "r"(u));
    return d;
}
__device__ __forceinline__ float2 unpack2(ull a) {
    float2 r;
    asm("mov.b64 {%0, %1}, %2;" : "=f"(r.x), "=f"(r.y) : "l"(a));
    return r;
}

// ---------------- scratch (device globals; no allocations allowed) ----------------
__device__ float d_Bmat[Ff * HC];                 // gathered Ws:  [f][(e*M+m)*G+g]
__device__ float d_Wh[(size_t)ROWS * HC];         // [b*N+n][(e*M+m)*G+g]
__device__ float d_s1[EM * ROWS];                 // [(e*M+m)][b*N+n]
__device__ float d_s2[EM * ROWS];
__device__ float d_H[(size_t)ROWS * HC];          // [b*N+n][(m*E+e)*G+g]
__device__ float d_T1[ROWS * Ff];                 // Y1 / Y4 (pre-bn buffers, width 128)
__device__ float d_H2[ROWS * Ff];                 // post-bn1 H
__device__ float d_Ta[ROWS * L0c];                // width-256 buffer A
__device__ float d_Tb[ROWS * L0c];                // width-256 buffer B
__device__ float d_sum[256];
__device__ float d_sq[256];

// ---------------- Bmat gather: Bmat[f][(e*M+m)*G+g] = Ws[e][m*F+f][g] ----------------
__global__ void bmat_kernel(const float* __restrict__ Ws) {
    int idx = blockIdx.x * 256 + threadIdx.x;
    if (idx >= Ff * HC) return;
    int f = idx / HC, c = idx % HC;
    int em = c >> 6, g = c & 63;
    int e = em >> 2, m = em & 3;
    d_Bmat[idx] = Ws[((size_t)e * (Mm * Ff) + m * Ff + f) * Gg + g];
}

// ---------------- generic tiled fp32 GEMM: C = alpha*(A@B) + beta*D ----------------
// 64x64 tile, 256 threads, 4x4 per thread, fma.rn.f32x2 inner loop.
// gridDim = (NC/64, Mrows/64). K % 16 == 0, NC % 64 == 0.
__global__ __launch_bounds__(256) void gemm_kernel(
    const float* __restrict__ A, const float* __restrict__ Bm,
    const float* __restrict__ D, float* __restrict__ C,
    float alpha, float beta, int K, int NC)
{
    __shared__ __align__(16) float sA[16][64];
    __shared__ __align__(16) float sB[16][64];
    int t  = threadIdx.x;
    int r0 = blockIdx.y * 64;
    int c0 = blockIdx.x * 64;
    int ty = t >> 4, tx = t & 15;
    int i0 = ty * 4, g0 = tx * 4;

    ull acc[4][2];
#pragma unroll
    for (int ii = 0; ii < 4; ii++) { acc[ii][0] = 0ull; acc[ii][1] = 0ull; }

    int la_i = t >> 2;          // 0..63
    int la_k = (t & 3) * 4;     // 0,4,8,12
    int lb_k = t >> 4;          // 0..15
    int lb_c = (t & 15) * 4;    // 0..60

    for (int k0 = 0; k0 < K; k0 += 16) {
        __syncthreads();
        float4 av = *(const float4*)&A[(size_t)(r0 + la_i) * K + k0 + la_k];
        sA[la_k + 0][la_i] = av.x;
        sA[la_k + 1][la_i] = av.y;
        sA[la_k + 2][la_i] = av.z;
        sA[la_k + 3][la_i] = av.w;
        *(float4*)&sB[lb_k][lb_c] =
            *(const float4*)&Bm[(size_t)(k0 + lb_k) * NC + c0 + lb_c];
        __syncthreads();
#pragma unroll
        for (int kk = 0; kk < 16; kk++) {
            ulonglong2 bp = *(const ulonglong2*)&sB[kk][g0];
#pragma unroll
            for (int ii = 0; ii < 4; ii++) {
                ull ap = pack2(sA[kk][i0 + ii]);
                acc[ii][0] = fma2(ap, bp.x, acc[ii][0]);
                acc[ii][1] = fma2(ap, bp.y, acc[ii][1]);
            }
        }
    }
#pragma unroll
    for (int ii = 0; ii < 4; ii++) {
        float2 v0 = unpack2(acc[ii][0]);
        float2 v1 = unpack2(acc[ii][1]);
        float4 o;
        o.x = alpha * v0.x; o.y = alpha * v0.y;
        o.z = alpha * v1.x; o.w = alpha * v1.y;
        size_t off = (size_t)(r0 + i0 + ii) * NC + c0 + g0;
        if (D) {
            float4 dv = *(const float4*)&D[off];
            o.x += beta * dv.x; o.y += beta * dv.y;
            o.z += beta * dv.z; o.w += beta * dv.w;
        }
        *(float4*)&C[off] = o;
    }
}

// ---------------- s1/s2: per-(row, e, m) dots of Wh with a1/a2 ----------------
__global__ void s12_kernel(const float* __restrict__ a1, const float* __restrict__ a2) {
    int w = (blockIdx.x * blockDim.x + threadIdx.x) >> 5;
    int lane = threadIdx.x & 31;
    if (w >= ROWS * EM) return;
    int row = w / EM;
    int em  = w % EM;
    int e = em >> 2, m = em & 3;
    const float* wh  = d_Wh + (size_t)row * HC + em * Gg;
    const float* av1 = a1 + e * (Mm * Gg) + m * Gg;
    const float* av2 = a2 + e * (Mm * Gg) + m * Gg;
    float x0 = wh[lane], x1 = wh[lane + 32];
    float v1 = x0 * av1[lane] + x1 * av1[lane + 32];
    float v2 = x0 * av2[lane] + x1 * av2[lane + 32];
#pragma unroll
    for (int off = 16; off; off >>= 1) {
        v1 += __shfl_xor_sync(0xffffffffu, v1, off);
        v2 += __shfl_xor_sync(0xffffffffu, v2, off);
    }
    if (lane == 0) {
        d_s1[(size_t)em * ROWS + row] = v1;
        d_s2[(size_t)em * ROWS + row] = v2;
    }
}

// ---------------- attention: one CTA per (b, e, m, 64-row i-tile) ----------------
// pass1: masked online (max, sumexp) per row.  pass2: p = exp(v-max)/sum, acc += p*Wh.
__global__ __launch_bounds__(256) void attn_kernel(const int* __restrict__ A) {
    int bx = blockIdx.x;          // iTile*M + m  (heads adjacent -> mask L2 reuse)
    int m  = bx & 3;
    int iT = bx >> 2;             // 0..15
    int e  = blockIdx.y;
    int b  = blockIdx.z;
    int em = e * Mm + m;
    int i0base = iT * 64;

    const int*   maskBase = A + ((size_t)(b * Ee + e) * Nn + i0base) * Nn;
    const float* s1p = d_s1 + (size_t)em * ROWS + b * Nn + i0base;
    const float* s2p = d_s2 + (size_t)em * ROWS + b * Nn;
    const float* WhB = d_Wh + (size_t)b * Nn * HC + em * Gg;

    __shared__ __align__(16) float sWh[64][64];
    __shared__ __align__(16) float sP[64][64];
    __shared__ __align__(16) float sS2[1024];
    __shared__ float sS1[64];
    __shared__ float sMax[64];
    __shared__ float sInv[64];

    int t = threadIdx.x;
    for (int idx = t; idx < 256; idx += 256)
        *(float4*)&sS2[idx * 4] = *(const float4*)&s2p[idx * 4];
    if (t < 64) sS1[t] = s1p[t];
    __syncthreads();

    // ---- pass 1: per-row max + sum of exp (4 lanes per row) ----
    {
        int r = t >> 2, q = t & 3;
        float s1v = sS1[r];
        const int* mrow = maskBase + (size_t)r * Nn;
        float mx = -3.0e38f, sm = 0.f;
        for (int k = 0; k < 64; k++) {
            int j0 = k * 16 + q * 4;
            int4   mk  = *(const int4*)&mrow[j0];
            float4 s2v = *(const float4*)&sS2[j0];
            float vv[4];
            int   mm_[4];
            vv[0] = s2v.x; vv[1] = s2v.y; vv[2] = s2v.z; vv[3] = s2v.w;
            mm_[0] = mk.x; mm_[1] = mk.y; mm_[2] = mk.z; mm_[3] = mk.w;
#pragma unroll
            for (int u = 0; u < 4; u++) {
                float v = s1v + vv[u];
                v = v > 0.f ? v : 0.01f * v;     // leaky_relu(0.01)
                if (mm_[u] <= 0) v = NEGV;
                if (v > mx) { sm *= __expf(mx - v); mx = v; }
                sm += __expf(v - mx);
            }
        }
#pragma unroll
        for (int off = 1; off < 4; off <<= 1) {
            float om = __shfl_xor_sync(0xffffffffu, mx, off);
            float os = __shfl_xor_sync(0xffffffffu, sm, off);
            float nm = fmaxf(mx, om);
            sm = sm * __expf(mx - nm) + os * __expf(om - nm);
            mx = nm;
        }
        if (q == 0) { sMax[r] = mx; sInv[r] = 1.0f / sm; }
    }

    // ---- pass 2: accumulate softmax @ Wh with f32x2 FMA ----
    int ty = t >> 4, tx = t & 15;
    int i0 = ty * 4, g0 = tx * 4;
    ull acc[4][2];
#pragma unroll
    for (int ii = 0; ii < 4; ii++) { acc[ii][0] = 0ull; acc[ii][1] = 0ull; }

    int wj = t >> 2;              // Wh loader row 0..63
    int wg = (t & 3) * 16;        // Wh loader col seg

    for (int jt = 0; jt < 16; jt++) {
        int jb = jt * 64;
        __syncthreads();
        {   // load Wh tile [64 x 64]
            const float* src = &WhB[(size_t)(jb + wj) * HC + wg];
            float4 v0 = *(const float4*)&src[0];
            float4 v1 = *(const float4*)&src[4];
            float4 v2 = *(const float4*)&src[8];
            float4 v3 = *(const float4*)&src[12];
            *(float4*)&sWh[wj][wg + 0]  = v0;
            *(float4*)&sWh[wj][wg + 4]  = v1;
            *(float4*)&sWh[wj][wg + 8]  = v2;
            *(float4*)&sWh[wj][wg + 12] = v3;
        }
        // compute p tile [64 x 64]
#pragma unroll
        for (int rep = 0; rep < 16; rep++) {
            int idx = rep * 256 + t;
            int i = idx >> 6, j = idx & 63;
            int msk = maskBase[(size_t)i * Nn + jb + j];
            float v = sS1[i] + sS2[jb + j];
            v = v > 0.f ? v : 0.01f * v;
            float p = (msk > 0) ? __expf(v - sMax[i]) * sInv[i] : 0.f;
            sP[i][j] = p;
        }
        __syncthreads();
#pragma unroll 16
        for (int jj = 0; jj < 64; jj++) {
            ulonglong2 wp = *(const ulonglong2*)&sWh[jj][g0];
#pragma unroll
            for (int ii = 0; ii < 4; ii++) {
                ull pp = pack2(sP[i0 + ii][jj]);
                acc[ii][0] = fma2(pp, wp.x, acc[ii][0]);
                acc[ii][1] = fma2(pp, wp.y, acc[ii][1]);
            }
        }
    }

    // ---- epilogue: elu, write H with head-major column layout (m*E+e) ----
    float* Hout = d_H + (size_t)(b * Nn + i0base) * HC + (m * Ee + e) * Gg;
#pragma unroll
    for (int ii = 0; ii < 4; ii++) {
        float2 v0 = unpack2(acc[ii][0]);
        float2 v1 = unpack2(acc[ii][1]);
        float4 o;
        o.x = v0.x > 0.f ? v0.x : expm1f(v0.x);
        o.y = v0.y > 0.f ? v0.y : expm1f(v0.y);
        o.z = v1.x > 0.f ? v1.x : expm1f(v1.x);
        o.w = v1.y > 0.f ? v1.y : expm1f(v1.y);
        *(float4*)&Hout[(size_t)(i0 + ii) * HC + g0] = o;
    }
}

// ---------------- batch-norm stats (axis 0 over ROWS) ----------------
__global__ void zero_stats() {
    int t = threadIdx.x;
    if (t < 256) { d_sum[t] = 0.f; d_sq[t] = 0.f; }
}

// grid = 128 blocks x 256 threads; block handles 64 rows; coalesced reads + atomics
__global__ void colstats_kernel(const float* __restrict__ Y, int cols) {
    __shared__ float ssum[256], ssq[256];
    int t = threadIdx.x;
    int col  = t % cols;
    int rsub = t / cols;
    int rpt  = 256 / cols;
    float s = 0.f, q = 0.f;
    int rbase = blockIdx.x * 64;
    for (int r = rsub; r < 64; r += rpt) {
        float v = Y[(size_t)(rbase + r) * cols + col];
        s += v; q += v * v;
    }
    ssum[t] = s; ssq[t] = q;
    __syncthreads();
    if (t < cols) {
        float S = 0.f, Q = 0.f;
        for (int u = t; u < 256; u += cols) { S += ssum[u]; Q += ssq[u]; }
        atomicAdd(&d_sum[t], S);
        atomicAdd(&d_sq[t], Q);
    }
}

// normalize (+ optional elu)
__global__ void bn_apply_kernel(const float* __restrict__ Y, float* __restrict__ Out,
                                const float* __restrict__ g, const float* __restrict__ bta,
                                int cols, int act) {
    int idx = blockIdx.x * 256 + threadIdx.x;
    if (idx >= ROWS * cols) return;
    int col = idx & (cols - 1);               // cols is a power of two (128/256)
    const float inv = 1.0f / (float)ROWS;
    float mu  = d_sum[col] * inv;
    float var = d_sq[col] * inv - mu * mu;
    float x = (Y[idx] - mu) * rsqrtf(var + EPSc) * g[col] + bta[col];
    if (act) x = x > 0.f ? x : expm1f(x);
    Out[idx] = x;
}

// ---------------- edge_cat: out[b][i][j][e] = (float)A[b][e][i][j] ----------------
__global__ void edge_kernel(const int* __restrict__ A, float* __restrict__ out) {
    int idx = blockIdx.x * 256 + threadIdx.x;   // over B*N*N
    if (idx >= Bq * Nn * Nn) return;
    int b   = idx >> 20;
    int rem = idx & ((1 << 20) - 1);            // i*N + j
    const int* base = A + (size_t)b * Ee * Nn * Nn + rem;
    out[(size_t)idx * 3 + 0] = (float)base[0];
    out[(size_t)idx * 3 + 1] = (float)base[Nn * Nn];
    out[(size_t)idx * 3 + 2] = (float)base[2 * Nn * Nn];
}

// ---------------- launcher ----------------
extern "C" void kernel_launch(void* const* d_in, const int* in_sizes, int n_in,
                              void* d_out, int out_size)
{
    const int*   A     = (const int*)  d_in[0];
    const float* X     = (const float*)d_in[1];
    /* d_in[2] = mini_batch (unused) */
    const float* Ws    = (const float*)d_in[3];
    const float* a1    = (const float*)d_in[4];
    const float* a2    = (const float*)d_in[5];
    const float* W1    = (const float*)d_in[6];
    const float* bn1g  = (const float*)d_in[7];
    const float* bn1b  = (const float*)d_in[8];
    const float* el0   = (const float*)d_in[9];
    const float* ebn0g = (const float*)d_in[10];
    const float* ebn0b = (const float*)d_in[11];
    const float* el1   = (const float*)d_in[12];
    const float* ebn1g = (const float*)d_in[13];
    const float* ebn1b = (const float*)d_in[14];
    const float* el2   = (const float*)d_in[15];
    const float* bn2g  = (const float*)d_in[16];
    const float* bn2b  = (const float*)d_in[17];
    float* out = (float*)d_out;

    float *pBmat, *pWh, *pH, *pT1, *pH2, *pTa, *pTb;
    cudaGetSymbolAddress((void**)&pBmat, d_Bmat);
    cudaGetSymbolAddress((void**)&pWh,   d_Wh);
    cudaGetSymbolAddress((void**)&pH,    d_H);
    cudaGetSymbolAddress((void**)&pT1,   d_T1);
    cudaGetSymbolAddress((void**)&pH2,   d_H2);
    cudaGetSymbolAddress((void**)&pTa,   d_Ta);
    cudaGetSymbolAddress((void**)&pTb,   d_Tb);

    // 1) gather Ws -> Bmat ; Wh = X @ Bmat   (8192 x 128 x 768)
    bmat_kernel<<<(Ff * HC + 255) / 256, 256>>>(Ws);
    gemm_kernel<<<dim3(HC / 64, ROWS / 64), 256>>>(X, pBmat, nullptr, pWh, 1.f, 0.f, Ff, HC);

    // 2) s1/s2
    s12_kernel<<<(ROWS * EM * 32) / 256, 256>>>(a1, a2);

    // 3) attention -> H
    attn_kernel<<<dim3((Nn / 64) * Mm, Ee, Bq), 256>>>(A);

    // 4) Y1 = 0.5*(H@W1) + 0.5*X ; bn1 -> H2
    gemm_kernel<<<dim3(Ff / 64, ROWS / 64), 256>>>(pH, W1, X, pT1, 1.f - ALPHAc, ALPHAc, HC, Ff);
    zero_stats<<<1, 256>>>();
    colstats_kernel<<<128, 256>>>(pT1, Ff);
    bn_apply_kernel<<<(ROWS * Ff) / 256, 256>>>(pT1, pH2, bn1g, bn1b, Ff, 0);

    // 5) Z0 = elu(bn(H2 @ e_l0))
    gemm_kernel<<<dim3(L0c / 64, ROWS / 64), 256>>>(pH2, el0, nullptr, pTa, 1.f, 0.f, Ff, L0c);
    zero_stats<<<1, 256>>>();
    colstats_kernel<<<128, 256>>>(pTa, L0c);
    bn_apply_kernel<<<(ROWS * L0c) / 256, 256>>>(pTa, pTb, ebn0g, ebn0b, L0c, 1);

    // 6) Z1 = elu(bn(Z0 @ e_l1))
    gemm_kernel<<<dim3(L1c / 64, ROWS / 64), 256>>>(pTb, el1, nullptr, pTa, 1.f, 0.f, L0c, L1c);
    zero_stats<<<1, 256>>>();
    colstats_kernel<<<128, 256>>>(pTa, L1c);
    bn_apply_kernel<<<(ROWS * L1c) / 256, 256>>>(pTa, pTb, ebn1g, ebn1b, L1c, 1);

    // 7) Y4 = Z1 @ e_l2 + H2 ; Z = bn2(Y4) -> out
    gemm_kernel<<<dim3(Ff / 64, ROWS / 64), 256>>>(pTb, el2, pH2, pT1, 1.f, 1.f, L1c, Ff);
    zero_stats<<<1, 256>>>();
    colstats_kernel<<<128, 256>>>(pT1, Ff);
    bn_apply_kernel<<<(ROWS * Ff) / 256, 256>>>(pT1, out, bn2g, bn2b, Ff, 0);

    // 8) edge_cat -> out[B*N*F ...]
    edge_kernel<<<(Bq * Nn * Nn + 255) / 256, 256>>>(A, out + (size_t)ROWS * Ff);
}

// round 8
// speedup vs baseline: 1.2211x; 1.2211x over previous
#include <cuda_runtime.h>
#include <math.h>
#include <cstdint>

// ---------------- problem constants ----------------
#define Bq    8
#define Nn    1024
#define Ff    128
#define Gg    64
#define Mm    4
#define Ee    3
#define EM    12          // E*M
#define HC    768         // M*E*G (hidden width)
#define ROWS  8192        // B*N
#define L0c   256
#define L1c   256
#define ALPHAc 0.5f
#define EPSc  1e-5f

typedef unsigned long long ull;

// ---------------- f32x2 helpers ----------------
__device__ __forceinline__ ull fma2(ull a, ull b, ull c) {
    ull d;
    asm("fma.rn.f32x2 %0, %1, %2, %3;" : "=l"(d) : "l"(a), "l"(b), "l"(c));
    return d;
}
__device__ __forceinline__ ull pack2(float x) {
    ull d; unsigned u = __float_as_uint(x);
    asm("mov.b64 %0, {%1, %1};" : "=l"(d) : "r"(u));
    return d;
}
__device__ __forceinline__ float2 unpack2(ull a) {
    float2 r;
    asm("mov.b64 {%0, %1}, %2;" : "=f"(r.x), "=f"(r.y) : "l"(a));
    return r;
}
__device__ __forceinline__ uint32_t to_tf32(float x) {
    uint32_t r;
    asm("cvt.rna.tf32.f32 %0, %1;" : "=r"(r) : "f"(x));
    return r;
}
// m16n8k8 tf32 mma: D += A*B (fp32 accum)
__device__ __forceinline__ void mma_tf32(float* d, const uint32_t* a, uint32_t b0, uint32_t b1) {
    asm volatile(
        "mma.sync.aligned.m16n8k8.row.col.f32.tf32.tf32.f32 "
        "{%0,%1,%2,%3}, {%4,%5,%6,%7}, {%8,%9}, {%0,%1,%2,%3};"
        : "+f"(d[0]), "+f"(d[1]), "+f"(d[2]), "+f"(d[3])
        : "r"(a[0]), "r"(a[1]), "r"(a[2]), "r"(a[3]), "r"(b0), "r"(b1));
}

// ---------------- scratch ----------------
__device__ float d_Bmat[Ff * HC];
__device__ float d_Wh[(size_t)ROWS * HC];
__device__ float d_WhT[(size_t)HC * ROWS];        // [em*64+g][b*N+j]
__device__ float d_s1[EM * ROWS];
__device__ float d_s2[EM * ROWS];
__device__ float d_H[(size_t)ROWS * HC];
__device__ float d_T1[ROWS * Ff];
__device__ float d_H2[ROWS * Ff];
__device__ float d_Ta[ROWS * L0c];
__device__ float d_Tb[ROWS * L0c];
__device__ float d_sum[256];
__device__ float d_sq[256];

// ---------------- Bmat gather ----------------
__global__ void bmat_kernel(const float* __restrict__ Ws) {
    int idx = blockIdx.x * 256 + threadIdx.x;
    if (idx >= Ff * HC) return;
    int f = idx / HC, c = idx % HC;
    int em = c >> 6, g = c & 63;
    int e = em >> 2, m = em & 3;
    d_Bmat[idx] = Ws[((size_t)e * (Mm * Ff) + m * Ff + f) * Gg + g];
}

// ---------------- generic fp32 GEMM (packed-dup A in smem) ----------------
__global__ __launch_bounds__(256) void gemm_kernel(
    const float* __restrict__ A, const float* __restrict__ Bm,
    const float* __restrict__ D, float* __restrict__ C,
    float alpha, float beta, int K, int NC)
{
    __shared__ __align__(16) ull   sA2[16][64];
    __shared__ __align__(16) float sB[16][64];
    int t  = threadIdx.x;
    int r0 = blockIdx.y * 64;
    int c0 = blockIdx.x * 64;
    int ty = t >> 4, tx = t & 15;
    int i0 = ty * 4, g0 = tx * 4;

    ull acc[4][2];
#pragma unroll
    for (int ii = 0; ii < 4; ii++) { acc[ii][0] = 0ull; acc[ii][1] = 0ull; }

    int la_i = t >> 2;
    int la_k = (t & 3) * 4;
    int lb_k = t >> 4;
    int lb_c = (t & 15) * 4;

    for (int k0 = 0; k0 < K; k0 += 16) {
        __syncthreads();
        float4 av = *(const float4*)&A[(size_t)(r0 + la_i) * K + k0 + la_k];
        sA2[la_k + 0][la_i] = pack2(av.x);
        sA2[la_k + 1][la_i] = pack2(av.y);
        sA2[la_k + 2][la_i] = pack2(av.z);
        sA2[la_k + 3][la_i] = pack2(av.w);
        *(float4*)&sB[lb_k][lb_c] =
            *(const float4*)&Bm[(size_t)(k0 + lb_k) * NC + c0 + lb_c];
        __syncthreads();
#pragma unroll
        for (int kk = 0; kk < 16; kk++) {
            ulonglong2 bp = *(const ulonglong2*)&sB[kk][g0];
#pragma unroll
            for (int ii = 0; ii < 4; ii++) {
                ull ap = sA2[kk][i0 + ii];
                acc[ii][0] = fma2(ap, bp.x, acc[ii][0]);
                acc[ii][1] = fma2(ap, bp.y, acc[ii][1]);
            }
        }
    }
#pragma unroll
    for (int ii = 0; ii < 4; ii++) {
        float2 v0 = unpack2(acc[ii][0]);
        float2 v1 = unpack2(acc[ii][1]);
        float4 o;
        o.x = alpha * v0.x; o.y = alpha * v0.y;
        o.z = alpha * v1.x; o.w = alpha * v1.y;
        size_t off = (size_t)(r0 + i0 + ii) * NC + c0 + g0;
        if (D) {
            float4 dv = *(const float4*)&D[off];
            o.x += beta * dv.x; o.y += beta * dv.y;
            o.z += beta * dv.z; o.w += beta * dv.w;
        }
        *(float4*)&C[off] = o;
    }
}

// ---------------- Wh -> WhT transpose (32x32 tiles) ----------------
__global__ void transpose_kernel(const float* __restrict__ Wh, float* __restrict__ WhT) {
    __shared__ float tile[32][33];
    int x = blockIdx.x * 32 + threadIdx.x;          // HC col
    int y0 = blockIdx.y * 32;
#pragma unroll
    for (int q = 0; q < 32; q += 8)
        tile[threadIdx.y + q][threadIdx.x] = Wh[(size_t)(y0 + threadIdx.y + q) * HC + x];
    __syncthreads();
    int xo = blockIdx.y * 32 + threadIdx.x;         // ROWS col in output
    int yo0 = blockIdx.x * 32;
#pragma unroll
    for (int q = 0; q < 32; q += 8)
        WhT[(size_t)(yo0 + threadIdx.y + q) * ROWS + xo] = tile[threadIdx.x][threadIdx.y + q];
}

// ---------------- s1/s2 ----------------
__global__ void s12_kernel(const float* __restrict__ a1, const float* __restrict__ a2) {
    int w = (blockIdx.x * blockDim.x + threadIdx.x) >> 5;
    int lane = threadIdx.x & 31;
    if (w >= ROWS * EM) return;
    int row = w / EM;
    int em  = w % EM;
    int e = em >> 2, m = em & 3;
    const float* wh  = d_Wh + (size_t)row * HC + em * Gg;
    const float* av1 = a1 + e * (Mm * Gg) + m * Gg;
    const float* av2 = a2 + e * (Mm * Gg) + m * Gg;
    float x0 = wh[lane], x1 = wh[lane + 32];
    float v1 = x0 * av1[lane] + x1 * av1[lane + 32];
    float v2 = x0 * av2[lane] + x1 * av2[lane + 32];
#pragma unroll
    for (int off = 16; off; off >>= 1) {
        v1 += __shfl_xor_sync(0xffffffffu, v1, off);
        v2 += __shfl_xor_sync(0xffffffffu, v2, off);
    }
    if (lane == 0) {
        d_s1[(size_t)em * ROWS + row] = v1;
        d_s2[(size_t)em * ROWS + row] = v2;
    }
}

// ---------------- mma.sync tf32 attention ----------------
// CTA = (b, e, m, 128-row i-tile). 8 warps; warp w owns rows [16w,16w+16) x 64 cols.
// Single pass over j (32-wide tiles): P = exp(leaky(s1+s2))*mask generated into
// fragment-ordered smem (tf32), HMMA accumulates unnormalized; epilogue scales
// by 1/rowsum and applies elu.
__global__ __launch_bounds__(256, 2) void attn_mma_kernel(const int* __restrict__ Amask) {
    __shared__ __align__(16) uint32_t sPf[4096];   // [wt*4+c][lane][reg]  16KB
    __shared__ __align__(16) uint32_t sBf[2048];   // [nt][lane][c*2+slot]  8KB
    __shared__ float sS2[1024];
    __shared__ float sS1[128];
    __shared__ float sInv[128];

    int t = threadIdx.x;
    int wid = t >> 5, lane = t & 31;
    int m = blockIdx.x & 3, iT = blockIdx.x >> 2;
    int e = blockIdx.y, b = blockIdx.z;
    int em = e * Mm + m;
    int i0 = iT * 128;

    const float* s1p = d_s1 + (size_t)em * ROWS + b * Nn + i0;
    const float* s2p = d_s2 + (size_t)em * ROWS + b * Nn;
    if (t < 128) sS1[t] = s1p[t];
    for (int idx = t; idx < 256; idx += 256)
        *(float4*)&sS2[idx * 4] = *(const float4*)&s2p[idx * 4];
    __syncthreads();

    const int*   maskBase = Amask + ((size_t)(b * Ee + e) * Nn + i0) * Nn;
    const float* WhTB = d_WhT + (size_t)em * Gg * ROWS + b * Nn;

    // P-gen assignment: thread -> (row r, j-half jh)
    int r  = t >> 1;
    int jh = (t & 1) * 16;
    const int* mrow = maskBase + (size_t)r * Nn + jh;
    float s1v = sS1[r];
    float rowsum = 0.f;
    int wt = r >> 4;
    int rl = r & 7;           // lane row bits
    int rh = (r >> 3) & 1;    // reg row bit

    // B loader assignment: thread -> (g, j-quad)
    int bg = t >> 2, bjq = (t & 3) * 4;
    const float* bsrc = WhTB + (size_t)bg * ROWS;
    int bnt = bg >> 3;
    int blane4 = (bg & 7) << 2;

    float acc[8][4];
#pragma unroll
    for (int nt = 0; nt < 8; nt++)
#pragma unroll
        for (int q = 0; q < 4; q++) acc[nt][q] = 0.f;

    for (int tile = 0; tile < 32; tile++) {
        int j0 = tile * 32;
        __syncthreads();   // previous consume finished

        // ---- B tile: WhT[g][j0..j0+31] -> fragment-ordered sBf ----
        {
            float4 v0 = *(const float4*)&bsrc[j0 + bjq];
            float4 v1 = *(const float4*)&bsrc[j0 + bjq + 16];
            float vv[8] = {v0.x, v0.y, v0.z, v0.w, v1.x, v1.y, v1.z, v1.w};
#pragma unroll
            for (int u = 0; u < 8; u++) {
                int jj = (u < 4) ? (bjq + u) : (bjq + 12 + u);  // bjq+u or bjq+16+(u-4)
                int c = jj >> 3, k = jj & 7;
                sBf[bnt * 256 + (blane4 | (k & 3)) * 8 + c * 2 + (k >> 2)] = to_tf32(vv[u]);
            }
        }
        // ---- P tile -> fragment-ordered sPf (unnormalized exp) ----
#pragma unroll
        for (int q = 0; q < 4; q++) {
            int4   mk  = *(const int4*)&mrow[j0 + q * 4];
            float4 s2v = *(const float4*)&sS2[j0 + jh + q * 4];
            float pv[4];
            int   mm_[4] = {mk.x, mk.y, mk.z, mk.w};
            float sv[4] = {s2v.x, s2v.y, s2v.z, s2v.w};
#pragma unroll
            for (int u = 0; u < 4; u++) {
                float v = s1v + sv[u];
                v = fmaxf(v, 0.01f * v);
                float p = (mm_[u] > 0) ? __expf(v) : 0.f;
                pv[u] = p;
                rowsum += p;
                int j = jh + q * 4 + u;
                int c = j >> 3, k = j & 7;
                sPf[((wt * 4 + c) * 32 + ((rl << 2) | (k & 3))) * 4 + (rh + ((k >> 2) << 1))] = to_tf32(p);
            }
        }
        __syncthreads();

        // ---- consume: 4 k8-chunks, 8 n-tiles ----
        uint32_t a[4][4];
#pragma unroll
        for (int c = 0; c < 4; c++)
            *(uint4*)a[c] = *(const uint4*)&sPf[((wid * 4 + c) * 32 + lane) * 4];
#pragma unroll
        for (int nt = 0; nt < 8; nt++) {
            uint4 bA = *(const uint4*)&sBf[nt * 256 + lane * 8];
            uint4 bB = *(const uint4*)&sBf[nt * 256 + lane * 8 + 4];
            mma_tf32(acc[nt], a[0], bA.x, bA.y);
            mma_tf32(acc[nt], a[1], bA.z, bA.w);
            mma_tf32(acc[nt], a[2], bB.x, bB.y);
            mma_tf32(acc[nt], a[3], bB.z, bB.w);
        }
    }

    // ---- rowsum -> sInv ----
    rowsum += __shfl_xor_sync(0xffffffffu, rowsum, 1);
    if ((t & 1) == 0) sInv[r] = 1.0f / rowsum;
    __syncthreads();

    // ---- epilogue: scale + elu + store ----
    int r0 = wid * 16 + (lane >> 2);
    int r1 = r0 + 8;
    float inv0 = sInv[r0];
    float inv1 = sInv[r1];
    float* H0 = d_H + (size_t)(b * Nn + i0 + r0) * HC + (m * Ee + e) * Gg;
    float* H1 = d_H + (size_t)(b * Nn + i0 + r1) * HC + (m * Ee + e) * Gg;
    int cb = (lane & 3) * 2;
#pragma unroll
    for (int nt = 0; nt < 8; nt++) {
        float2 o0, o1;
        float x0 = acc[nt][0] * inv0, x1 = acc[nt][1] * inv0;
        float x2 = acc[nt][2] * inv1, x3 = acc[nt][3] * inv1;
        o0.x = x0 > 0.f ? x0 : expm1f(x0);
        o0.y = x1 > 0.f ? x1 : expm1f(x1);
        o1.x = x2 > 0.f ? x2 : expm1f(x2);
        o1.y = x3 > 0.f ? x3 : expm1f(x3);
        *(float2*)&H0[nt * 8 + cb] = o0;
        *(float2*)&H1[nt * 8 + cb] = o1;
    }
}

// ---------------- batch-norm ----------------
__global__ void zero_stats() {
    int t = threadIdx.x;
    if (t < 256) { d_sum[t] = 0.f; d_sq[t] = 0.f; }
}

__global__ void colstats_kernel(const float* __restrict__ Y, int cols) {
    __shared__ float ssum[256], ssq[256];
    int t = threadIdx.x;
    int col  = t % cols;
    int rsub = t / cols;
    int rpt  = 256 / cols;
    float s = 0.f, q = 0.f;
    int rbase = blockIdx.x * 64;
    for (int r = rsub; r < 64; r += rpt) {
        float v = Y[(size_t)(rbase + r) * cols + col];
        s += v; q += v * v;
    }
    ssum[t] = s; ssq[t] = q;
    __syncthreads();
    if (t < cols) {
        float S = 0.f, Q = 0.f;
        for (int u = t; u < 256; u += cols) { S += ssum[u]; Q += ssq[u]; }
        atomicAdd(&d_sum[t], S);
        atomicAdd(&d_sq[t], Q);
    }
}

__global__ void bn_apply_kernel(const float* __restrict__ Y, float* __restrict__ Out,
                                const float* __restrict__ g, const float* __restrict__ bta,
                                int cols, int act) {
    int idx = blockIdx.x * 256 + threadIdx.x;
    if (idx >= ROWS * cols) return;
    int col = idx & (cols - 1);
    const float inv = 1.0f / (float)ROWS;
    float mu  = d_sum[col] * inv;
    float var = d_sq[col] * inv - mu * mu;
    float x = (Y[idx] - mu) * rsqrtf(var + EPSc) * g[col] + bta[col];
    if (act) x = x > 0.f ? x : expm1f(x);
    Out[idx] = x;
}

// ---------------- edge_cat ----------------
__global__ void edge_kernel(const int* __restrict__ A, float* __restrict__ out) {
    int idx = blockIdx.x * 256 + threadIdx.x;
    if (idx >= Bq * Nn * Nn) return;
    int b   = idx >> 20;
    int rem = idx & ((1 << 20) - 1);
    const int* base = A + (size_t)b * Ee * Nn * Nn + rem;
    out[(size_t)idx * 3 + 0] = (float)base[0];
    out[(size_t)idx * 3 + 1] = (float)base[Nn * Nn];
    out[(size_t)idx * 3 + 2] = (float)base[2 * Nn * Nn];
}

// ---------------- launcher ----------------
extern "C" void kernel_launch(void* const* d_in, const int* in_sizes, int n_in,
                              void* d_out, int out_size)
{
    const int*   A     = (const int*)  d_in[0];
    const float* X     = (const float*)d_in[1];
    const float* Ws    = (const float*)d_in[3];
    const float* a1    = (const float*)d_in[4];
    const float* a2    = (const float*)d_in[5];
    const float* W1    = (const float*)d_in[6];
    const float* bn1g  = (const float*)d_in[7];
    const float* bn1b  = (const float*)d_in[8];
    const float* el0   = (const float*)d_in[9];
    const float* ebn0g = (const float*)d_in[10];
    const float* ebn0b = (const float*)d_in[11];
    const float* el1   = (const float*)d_in[12];
    const float* ebn1g = (const float*)d_in[13];
    const float* ebn1b = (const float*)d_in[14];
    const float* el2   = (const float*)d_in[15];
    const float* bn2g  = (const float*)d_in[16];
    const float* bn2b  = (const float*)d_in[17];
    float* out = (float*)d_out;

    float *pBmat, *pWh, *pWhT, *pH, *pT1, *pH2, *pTa, *pTb;
    cudaGetSymbolAddress((void**)&pBmat, d_Bmat);
    cudaGetSymbolAddress((void**)&pWh,   d_Wh);
    cudaGetSymbolAddress((void**)&pWhT,  d_WhT);
    cudaGetSymbolAddress((void**)&pH,    d_H);
    cudaGetSymbolAddress((void**)&pT1,   d_T1);
    cudaGetSymbolAddress((void**)&pH2,   d_H2);
    cudaGetSymbolAddress((void**)&pTa,   d_Ta);
    cudaGetSymbolAddress((void**)&pTb,   d_Tb);

    // 1) Bmat gather ; Wh = X @ Bmat ; WhT
    bmat_kernel<<<(Ff * HC + 255) / 256, 256>>>(Ws);
    gemm_kernel<<<dim3(HC / 64, ROWS / 64), 256>>>(X, pBmat, nullptr, pWh, 1.f, 0.f, Ff, HC);
    transpose_kernel<<<dim3(HC / 32, ROWS / 32), dim3(32, 8)>>>(pWh, pWhT);

    // 2) s1/s2
    s12_kernel<<<(ROWS * EM * 32) / 256, 256>>>(a1, a2);

    // 3) attention (mma.sync tf32) -> H
    attn_mma_kernel<<<dim3((Nn / 128) * Mm, Ee, Bq), 256>>>(A);

    // 4) Y1 = 0.5*(H@W1) + 0.5*X ; bn1 -> H2
    gemm_kernel<<<dim3(Ff / 64, ROWS / 64), 256>>>(pH, W1, X, pT1, 1.f - ALPHAc, ALPHAc, HC, Ff);
    zero_stats<<<1, 256>>>();
    colstats_kernel<<<128, 256>>>(pT1, Ff);
    bn_apply_kernel<<<(ROWS * Ff) / 256, 256>>>(pT1, pH2, bn1g, bn1b, Ff, 0);

    // 5) Z0 = elu(bn(H2 @ e_l0))
    gemm_kernel<<<dim3(L0c / 64, ROWS / 64), 256>>>(pH2, el0, nullptr, pTa, 1.f, 0.f, Ff, L0c);
    zero_stats<<<1, 256>>>();
    colstats_kernel<<<128, 256>>>(pTa, L0c);
    bn_apply_kernel<<<(ROWS * L0c) / 256, 256>>>(pTa, pTb, ebn0g, ebn0b, L0c, 1);

    // 6) Z1 = elu(bn(Z0 @ e_l1))
    gemm_kernel<<<dim3(L1c / 64, ROWS / 64), 256>>>(pTb, el1, nullptr, pTa, 1.f, 0.f, L0c, L1c);
    zero_stats<<<1, 256>>>();
    colstats_kernel<<<128, 256>>>(pTa, L1c);
    bn_apply_kernel<<<(ROWS * L1c) / 256, 256>>>(pTa, pTb, ebn1g, ebn1b, L1c, 1);

    // 7) Y4 = Z1 @ e_l2 + H2 ; bn2 -> out
    gemm_kernel<<<dim3(Ff / 64, ROWS / 64), 256>>>(pTb, el2, pH2, pT1, 1.f, 1.f, L1c, Ff);
    zero_stats<<<1, 256>>>();
    colstats_kernel<<<128, 256>>>(pT1, Ff);
    bn_apply_kernel<<<(ROWS * Ff) / 256, 256>>>(pT1, out, bn2g, bn2b, Ff, 0);

    // 8) edge_cat
    edge_kernel<<<(Bq * Nn * Nn + 255) / 256, 256>>>(A, out + (size_t)ROWS * Ff);
}